// round 15
// baseline (speedup 1.0000x reference)
#include <cuda_runtime.h>
#include <cuda.h>
#include <cuda_bf16.h>
#include <cuda_fp16.h>
#include <math.h>
#include <stdint.h>

// Problem constants
#define Bsz 4
#define Ssz 2048
#define Hsz 1024
#define Nh  16
#define Dh  64
#define Msz (Bsz*Ssz)      // 8192
#define EPSF 1e-6f

// ---------------- scratch (static device globals; no allocs allowed) -------
__device__ __half g_q16[Msz*Hsz];         // q (phi'd, scaled) fp16 [s][1024]
__device__ __half g_kt[64*64*Ssz];        // k transposed [bn][kd][s] fp16
__device__ __half g_vt[64*64*Ssz];        // v transposed [bn][vd][s] fp16
__device__ float g_kv_part[4*64*64*64];   // [kc][bn][vd][kd]
__device__ __half g_kvt_h[64*72*64];      // [bn][72][64]: rows0-63 kv, 64 ksum
__device__ __half g_kvt_l[64*72*64];
__device__ float g_gate[Msz];
__device__ float2 g_rope[Ssz*32];         // (cos, sin) per (s, i)
__device__ __half g_af[Msz*Hsz];          // x fp16 (QKV phase), comb fp16 after
__device__ __half g_bq16[Hsz*Hsz];        // Wq single fp16 [N][K]
__device__ __half g_bk16[Hsz*Hsz];
__device__ __half g_bv16[Hsz*Hsz];
__device__ __half g_bo16[Hsz*Hsz];

// ================= low-level helpers =======================================
static __device__ __forceinline__ uint32_t s2u(const void* p) {
    uint32_t a;
    asm("{ .reg .u64 t; cvta.to.shared.u64 t, %1; cvt.u32.u64 %0, t; }"
        : "=r"(a) : "l"(p));
    return a;
}

static __device__ __forceinline__ void ldsm4(uint32_t* r, uint32_t addr) {
    asm volatile("ldmatrix.sync.aligned.m8n8.x4.shared.b16 {%0,%1,%2,%3}, [%4];"
                 : "=r"(r[0]), "=r"(r[1]), "=r"(r[2]), "=r"(r[3]) : "r"(addr));
}

static __device__ __forceinline__ void mma16816h(float* d, const uint32_t* a,
                                                 const uint32_t* b) {
    asm volatile(
        "mma.sync.aligned.m16n8k16.row.col.f32.f16.f16.f32 "
        "{%0,%1,%2,%3}, {%4,%5,%6,%7}, {%8,%9}, {%0,%1,%2,%3};"
        : "+f"(d[0]), "+f"(d[1]), "+f"(d[2]), "+f"(d[3])
        : "r"(a[0]), "r"(a[1]), "r"(a[2]), "r"(a[3]), "r"(b[0]), "r"(b[1]));
}

// 64B-row tile swizzle (TMA SW64 tiles: rows of 32 halves)
static __device__ __forceinline__ uint32_t swoff(int row, int c16) {
    return (uint32_t)(row * 64 + ((c16 ^ ((row >> 1) & 3)) << 4));
}
// 128B-row tile swizzle (plain-load tiles: rows of 64 halves, 8 c16 chunks)
static __device__ __forceinline__ uint32_t swoff128(int row, int c16) {
    return (uint32_t)(row * 128 + ((c16 ^ (row & 7)) << 4));
}

#define MBAR_INIT(m, c) \
    asm volatile("mbarrier.init.shared.b64 [%0], %1;" \
                 :: "r"((uint32_t)(m)), "r"((uint32_t)(c)) : "memory")
#define MBAR_EXPECT(m, b) \
    asm volatile("mbarrier.arrive.expect_tx.shared.b64 _, [%0], %1;" \
                 :: "r"((uint32_t)(m)), "r"((uint32_t)(b)) : "memory")

static __device__ __forceinline__ void mbar_wait(uint32_t mbar, uint32_t parity) {
    asm volatile(
        "{\n\t.reg .pred P;\n\t"
        "WL_%=:\n\t"
        "mbarrier.try_wait.parity.acquire.cta.shared::cta.b64 P, [%0], %1, 0x989680;\n\t"
        "@P bra.uni WD_%=;\n\t"
        "bra.uni WL_%=;\n\t"
        "WD_%=:\n\t}"
        :: "r"(mbar), "r"(parity) : "memory");
}

#define TMA2D(sa, mp, cx, cy, mb) \
    asm volatile("cp.async.bulk.tensor.2d.shared::cta.global.tile.mbarrier::complete_tx::bytes " \
                 "[%0], [%1, {%2, %3}], [%4];" \
                 :: "r"((uint32_t)(sa)), "l"(mp), "r"((int)(cx)), "r"((int)(cy)), \
                    "r"((uint32_t)(mb)) : "memory")

__device__ __forceinline__ float phi_fn(float x) {
    float t = (x > 0.f) ? x : expm1f(x);
    return (t + 1.0f) + EPSF;
}

static __device__ __forceinline__ __half2 pack_h2(float a, float b) {
    return __halves2half2(__float2half(a), __float2half(b));
}

// ===== GEMM config: CTA tile 128x64, BK=64 stages, 3 stages, 3 CTA/SM =====
// stage 24KB: [A0 8K][A1 8K][B0 4K][B1 4K]
#define PSTAGES 3
#define PSTAGE_B 24576
#define NPAIR 16
#define SMEM_GEMM (PSTAGES * PSTAGE_B + 64)

// Warp tile 16x64: 8 warps cover M=128. acc[8][4] = 32 regs.
// Per K=16 slice: A 1 ldsm, B 4 ldsm, 8 MMAs, interleaved.
#define PAIR_BODY(bA, bB)                                                     \
    {                                                                         \
        uint32_t aF[2][4], br[4][4];                                          \
        {                                                                     \
            const int ks0 = wid & 3;                                          \
            ldsm4(aF[0], (bA) + (ks0 >> 1) * 8192 +                           \
                          swoff(a_row, (ks0 & 1) * 2 + a_c16h));              \
        }                                                                     \
        _Pragma("unroll")                                                     \
        for (int ksi = 0; ksi < 4; ksi++) {                                   \
            const int cur = ksi & 1, nxt = cur ^ 1;                           \
            const int ks = (ksi + wid) & 3;                                   \
            const uint32_t hB = (bB) + (ks >> 1) * 4096;                      \
            const int bc = (ks & 1) * 2 + b_c16h;                             \
            ldsm4(br[0], hB + swoff(b_row,      bc));                         \
            ldsm4(br[1], hB + swoff(b_row + 16, bc));                         \
            if (ksi < 3) {                                                    \
                const int ks2 = (ksi + 1 + wid) & 3;                          \
                ldsm4(aF[nxt], (bA) + (ks2 >> 1) * 8192 +                     \
                               swoff(a_row, (ks2 & 1) * 2 + a_c16h));         \
            }                                                                 \
            mma16816h(acc[0], aF[cur], br[0] + 0);                            \
            mma16816h(acc[1], aF[cur], br[0] + 2);                            \
            ldsm4(br[2], hB + swoff(b_row + 32, bc));                         \
            mma16816h(acc[2], aF[cur], br[1] + 0);                            \
            mma16816h(acc[3], aF[cur], br[1] + 2);                            \
            ldsm4(br[3], hB + swoff(b_row + 48, bc));                         \
            mma16816h(acc[4], aF[cur], br[2] + 0);                            \
            mma16816h(acc[5], aF[cur], br[2] + 2);                            \
            mma16816h(acc[6], aF[cur], br[3] + 0);                            \
            mma16816h(acc[7], aF[cur], br[3] + 2);                            \
        }                                                                     \
    }

// ========== QKV GEMM: single-product fp16 =================================
// z=0: q -> rope/phi*0.125, fp16 [s][1024]
// z=1: k -> rope/phi*mask, fp16 TRANSPOSED [bn][kd][s]
// z=2: v -> mask, fp16 TRANSPOSED [bn][vd][s]
__global__ __launch_bounds__(256, 3)
void gemm_qkv(const __grid_constant__ CUtensorMap mAf,
              const __grid_constant__ CUtensorMap mB0,
              const __grid_constant__ CUtensorMap mB1,
              const __grid_constant__ CUtensorMap mB2,
              const float* __restrict__ b0, const float* __restrict__ b1,
              const float* __restrict__ b2,
              __half* __restrict__ Cq, __half* __restrict__ KT,
              __half* __restrict__ VT,
              const float* __restrict__ maskp,
              const float2* __restrict__ tab)
{
    extern __shared__ __align__(1024) char smem[];
    const uint32_t sbase = s2u(smem);
    const uint32_t mbb  = sbase + PSTAGES * PSTAGE_B;
    const int tid = threadIdx.x;
    const int lane = tid & 31, wid = tid >> 5;
    const int n0 = blockIdx.x * 64, m0 = blockIdx.y * 128;
    const int z = blockIdx.z;

    const CUtensorMap* pB = (z == 0) ? &mB0 : (z == 1) ? &mB1 : &mB2;
    const float* bias = (z == 0) ? b0 : (z == 1) ? b1 : b2;

    const int a_row  = wid * 16 + (lane & 15);
    const int a_c16h = lane >> 4;
    const int b_row  = ((lane >> 4) << 3) + (lane & 7);
    const int b_c16h = (lane >> 3) & 1;

    float acc[8][4];
#pragma unroll
    for (int ni = 0; ni < 8; ni++)
#pragma unroll
        for (int u = 0; u < 4; u++) acc[ni][u] = 0.f;

    if (tid == 0) {
#pragma unroll
        for (int s = 0; s < PSTAGES; s++) MBAR_INIT(mbb + s * 8, 1);
    }
    __syncthreads();

    if (tid == 0) {
#pragma unroll
        for (int s = 0; s < PSTAGES; s++) {
            const uint32_t db = sbase + s * PSTAGE_B;
            MBAR_EXPECT(mbb + s * 8, PSTAGE_B);
            TMA2D(db,         &mAf, s * 64,      m0, mbb + s * 8);
            TMA2D(db + 8192,  &mAf, s * 64 + 32, m0, mbb + s * 8);
            TMA2D(db + 16384, pB,   s * 64,      n0, mbb + s * 8);
            TMA2D(db + 20480, pB,   s * 64 + 32, n0, mbb + s * 8);
        }
    }

    int sp = 0, ph = 0;
    for (int p = 0; p < NPAIR; p++) {
        mbar_wait(mbb + sp * 8, ph);

        const uint32_t bA = sbase + sp * PSTAGE_B;
        const uint32_t bB = bA + 16384;
        PAIR_BODY(bA, bB)

        __syncthreads();   // all threads done reading stage sp
        const int np_ = p + PSTAGES;
        if (np_ < NPAIR && tid == 0) {
            const uint32_t db = sbase + sp * PSTAGE_B;
            MBAR_EXPECT(mbb + sp * 8, PSTAGE_B);
            TMA2D(db,         &mAf, np_ * 64,      m0, mbb + sp * 8);
            TMA2D(db + 8192,  &mAf, np_ * 64 + 32, m0, mbb + sp * 8);
            TMA2D(db + 16384, pB,   np_ * 64,      n0, mbb + sp * 8);
            TMA2D(db + 20480, pB,   np_ * 64 + 32, n0, mbb + sp * 8);
        }
        if (++sp == PSTAGES) { sp = 0; ph ^= 1; }
    }

    // ---------------- epilogue ----------------
    const int r0 = m0 + wid * 16 + (lane >> 2);
    const int cb2 = 2 * (lane & 3);

    if (z == 0) {
#pragma unroll
        for (int uu = 0; uu < 4; uu += 2) {
            const int r = r0 + (uu ? 8 : 0);
            const int srow = r & (Ssz - 1);
#pragma unroll
            for (int ni = 0; ni < 4; ni++) {
                float o1[2], o2[2];
#pragma unroll
                for (int e = 0; e < 2; e++) {
                    const int i = cb2 + ni * 8 + e;   // 0..31 within head
                    const int c = n0 + i;
                    float x1 = acc[ni][uu + e]     + bias[c];
                    float x2 = acc[ni + 4][uu + e] + bias[c + 32];
                    float2 cs = tab[srow * 32 + i];
                    float r1 = x1 * cs.x - x2 * cs.y;
                    float r2 = x2 * cs.x + x1 * cs.y;
                    o1[e] = phi_fn(r1) * 0.125f;
                    o2[e] = phi_fn(r2) * 0.125f;
                }
                const int c = n0 + cb2 + ni * 8;
                *(__half2*)(Cq + (long)r * 1024 + c)      = pack_h2(o1[0], o1[1]);
                *(__half2*)(Cq + (long)r * 1024 + c + 32) = pack_h2(o2[0], o2[1]);
            }
        }
        return;
    }

    // k/v: transposed store via smem staging. ts[c_local(64)][rloc(128)], pitch 136
    __syncthreads();
    __half* ts = (__half*)smem;
    const int rb = wid * 16 + (lane >> 2);

#pragma unroll
    for (int uu = 0; uu < 4; uu += 2) {
        const int rloc = rb + (uu ? 8 : 0);
        const int r = m0 + rloc;
        const int srow = r & (Ssz - 1);
        const float msk = maskp[r];
        if (z == 2) {
#pragma unroll
            for (int ni = 0; ni < 8; ni++) {
#pragma unroll
                for (int e = 0; e < 2; e++) {
                    const int cl = cb2 + ni * 8 + e;
                    float val = (acc[ni][uu + e] + bias[n0 + cl]) * msk;
                    ts[cl * 136 + rloc] = __float2half(val);
                }
            }
        } else {
#pragma unroll
            for (int ni = 0; ni < 4; ni++) {
#pragma unroll
                for (int e = 0; e < 2; e++) {
                    const int i = cb2 + ni * 8 + e;
                    float x1 = acc[ni][uu + e]     + bias[n0 + i];
                    float x2 = acc[ni + 4][uu + e] + bias[n0 + i + 32];
                    float2 cs = tab[srow * 32 + i];
                    float r1 = x1 * cs.x - x2 * cs.y;
                    float r2 = x2 * cs.x + x1 * cs.y;
                    ts[i * 136 + rloc]        = __float2half(phi_fn(r1) * msk);
                    ts[(i + 32) * 136 + rloc] = __float2half(phi_fn(r2) * msk);
                }
            }
        }
    }
    __syncthreads();

    // coalesced write-out: [c][rloc] -> T[bn*64 + c][s]; 64x128 halves
    __half* T = (z == 1) ? KT : VT;
    const int b = m0 >> 11;
    const int sb = m0 & (Ssz - 1);
    const int bn = b * 16 + (n0 >> 6);
#pragma unroll
    for (int i = 0; i < 4; i++) {
        const int e = tid + i * 256;       // 0..1023
        const int c = e >> 4, ch = e & 15, rl = ch * 8;
        uint4 val = *(uint4*)&ts[c * 136 + rl];
        *(uint4*)(T + ((long)(bn * 64 + c)) * Ssz + sb + rl) = val;
    }
}

// ===== OUT GEMM: single-product fp16, same tile, fp32 store ================
__global__ __launch_bounds__(256, 3)
void gemm_out(const __grid_constant__ CUtensorMap mAf,
              const __grid_constant__ CUtensorMap mB,
              const float* __restrict__ bias, float* __restrict__ C)
{
    extern __shared__ __align__(1024) char smem[];
    const uint32_t sbase = s2u(smem);
    const uint32_t mbb  = sbase + PSTAGES * PSTAGE_B;
    const int tid = threadIdx.x;
    const int lane = tid & 31, wid = tid >> 5;
    const int n0 = blockIdx.x * 64, m0 = blockIdx.y * 128;

    const int a_row  = wid * 16 + (lane & 15);
    const int a_c16h = lane >> 4;
    const int b_row  = ((lane >> 4) << 3) + (lane & 7);
    const int b_c16h = (lane >> 3) & 1;

    float acc[8][4];
#pragma unroll
    for (int ni = 0; ni < 8; ni++)
#pragma unroll
        for (int u = 0; u < 4; u++) acc[ni][u] = 0.f;

    if (tid == 0) {
#pragma unroll
        for (int s = 0; s < PSTAGES; s++) MBAR_INIT(mbb + s * 8, 1);
    }
    __syncthreads();

    if (tid == 0) {
#pragma unroll
        for (int s = 0; s < PSTAGES; s++) {
            const uint32_t db = sbase + s * PSTAGE_B;
            MBAR_EXPECT(mbb + s * 8, PSTAGE_B);
            TMA2D(db,         &mAf, s * 64,      m0, mbb + s * 8);
            TMA2D(db + 8192,  &mAf, s * 64 + 32, m0, mbb + s * 8);
            TMA2D(db + 16384, &mB,  s * 64,      n0, mbb + s * 8);
            TMA2D(db + 20480, &mB,  s * 64 + 32, n0, mbb + s * 8);
        }
    }

    int sp = 0, ph = 0;
    for (int p = 0; p < NPAIR; p++) {
        mbar_wait(mbb + sp * 8, ph);

        const uint32_t bA = sbase + sp * PSTAGE_B;
        const uint32_t bB = bA + 16384;
        PAIR_BODY(bA, bB)

        __syncthreads();
        const int np_ = p + PSTAGES;
        if (np_ < NPAIR && tid == 0) {
            const uint32_t db = sbase + sp * PSTAGE_B;
            MBAR_EXPECT(mbb + sp * 8, PSTAGE_B);
            TMA2D(db,         &mAf, np_ * 64,      m0, mbb + sp * 8);
            TMA2D(db + 8192,  &mAf, np_ * 64 + 32, m0, mbb + sp * 8);
            TMA2D(db + 16384, &mB,  np_ * 64,      n0, mbb + sp * 8);
            TMA2D(db + 20480, &mB,  np_ * 64 + 32, n0, mbb + sp * 8);
        }
        if (++sp == PSTAGES) { sp = 0; ph ^= 1; }
    }

    const int r0 = m0 + wid * 16 + (lane >> 2);
    const int cb = n0 + 2 * (lane & 3);
#pragma unroll
    for (int ni = 0; ni < 8; ni++) {
        const int c = cb + ni * 8;
        float2 bb = *(const float2*)(bias + c);
        *(float2*)(C + (long)r0 * 1024 + c) =
            make_float2(acc[ni][0] + bb.x, acc[ni][1] + bb.y);
        *(float2*)(C + (long)(r0 + 8) * 1024 + c) =
            make_float2(acc[ni][2] + bb.x, acc[ni][3] + bb.y);
    }
}

// ============ gemm_kv: D[vd][kd] = sum_s v_t[vd][s] * k_t[kd][s] ===========
__global__ __launch_bounds__(256, 4)
void gemm_kv(const __half* __restrict__ vt, const __half* __restrict__ kt,
             float* __restrict__ part)
{
    __shared__ __align__(16) char sm[16384];
    const uint32_t sA = s2u(sm), sB = sA + 8192;
    const int tid = threadIdx.x;
    const int lane = tid & 31, wid = tid >> 5;
    const int wm = wid & 3, wn = wid >> 2;
    const int kc = blockIdx.x, head = blockIdx.y;

    float acc[4][4];
#pragma unroll
    for (int i = 0; i < 4; i++)
#pragma unroll
        for (int u = 0; u < 4; u++) acc[i][u] = 0.f;

    for (int sc = 0; sc < 8; sc++) {
        const int sg = kc * 512 + sc * 64;
#pragma unroll
        for (int j = 0; j < 4; j++) {
            const int e = tid + j * 256;
            const int t = e >> 9, row = (e >> 3) & 63, c16 = e & 7;
            const __half* src = (t ? kt : vt) +
                ((long)(head * 64 + row)) * Ssz + sg + c16 * 8;
            *(uint4*)((char*)sm + t * 8192 + swoff128(row, c16)) =
                *(const uint4*)src;
        }
        __syncthreads();

#pragma unroll
        for (int ks = 0; ks < 4; ks++) {
            uint32_t aF[4];
            ldsm4(aF, sA + swoff128(wm * 16 + (lane & 15), ks * 2 + (lane >> 4)));
#pragma unroll
            for (int nb = 0; nb < 2; nb++) {
                uint32_t bF[4];
                ldsm4(bF, sB + swoff128(wn * 32 + nb * 16 +
                                        ((lane >> 4) << 3) + (lane & 7),
                                        ks * 2 + ((lane >> 3) & 1)));
                mma16816h(acc[nb * 2 + 0], aF, bF + 0);
                mma16816h(acc[nb * 2 + 1], aF, bF + 2);
            }
        }
        __syncthreads();
    }

    float* pb = part + ((long)(kc * 64 + head)) * 4096;
    const int rb = wm * 16 + (lane >> 2);
    const int cb = wn * 32 + 2 * (lane & 3);
#pragma unroll
    for (int nf = 0; nf < 4; nf++) {
        const int c = cb + nf * 8;
        *(float2*)(pb + rb * 64 + c)       = make_float2(acc[nf][0], acc[nf][1]);
        *(float2*)(pb + (rb + 8) * 64 + c) = make_float2(acc[nf][2], acc[nf][3]);
    }
}

// ==== kvt_finalize: reduce partials -> kvt hi/lo; row64 = ksum; 65-71 = 0 ==
__global__ void kvt_finalize(const float* __restrict__ part,
                             const __half* __restrict__ kt,
                             __half* __restrict__ kvh, __half* __restrict__ kvl)
{
    const int head = blockIdx.x;
    const int tid = threadIdx.x;
    const long ob = (long)head * 72 * 64;

    for (int e = tid; e < 4096; e += 256) {
        float s = 0.f;
#pragma unroll
        for (int c = 0; c < 4; c++)
            s += part[((long)(c * 64 + head)) * 4096 + e];
        __half h = __float2half(s);
        kvh[ob + e] = h;
        kvl[ob + e] = __float2half(s - __half2float(h));
    }

    const int kd = tid >> 2, qtr = tid & 3;
    const __half* kr = kt + ((long)(head * 64 + kd)) * Ssz + qtr * 512;
    float s = 0.f;
#pragma unroll 8
    for (int i = 0; i < 64; i++) {
        uint4 u = *(const uint4*)(kr + i * 8);
        float2 a = __half22float2(*(__half2*)&u.x);
        float2 b = __half22float2(*(__half2*)&u.y);
        float2 c = __half22float2(*(__half2*)&u.z);
        float2 d = __half22float2(*(__half2*)&u.w);
        s += a.x + a.y + b.x + b.y + c.x + c.y + d.x + d.y;
    }
    s += __shfl_down_sync(0xffffffffu, s, 2);
    s += __shfl_down_sync(0xffffffffu, s, 1);
    if (qtr == 0) {
        __half h = __float2half(s);
        kvh[ob + 64 * 64 + kd] = h;
        kvl[ob + 64 * 64 + kd] = __float2half(s - __half2float(h));
    }

    for (int e = tid; e < 7 * 64; e += 256) {
        kvh[ob + 65 * 64 + e] = __float2half(0.f);
        kvl[ob + 65 * 64 + e] = __float2half(0.f);
    }
}

// ==== gemm_cmb: num/den = q @ kvt^T (hi+lo); gate epilogue -> comb fp16 ====
__global__ __launch_bounds__(256, 2)
void gemm_cmb(const __half* __restrict__ q,
              const __half* __restrict__ kvh, const __half* __restrict__ kvl,
              const float* __restrict__ gate,
              const float* __restrict__ df, const float* __restrict__ gw,
              __half* __restrict__ cf)
{
    __shared__ __align__(16) char sm[16384 + 2 * 10240];
    const uint32_t sA = s2u(sm);
    const uint32_t sBh = sA + 16384, sBl = sBh + 10240;
    const int tid = threadIdx.x;
    const int lane = tid & 31, wid = tid >> 5;
    const int mt = blockIdx.x, bn = blockIdx.y;
    const int b = bn >> 4, n = bn & 15;
    const long row0 = (long)b * Ssz + mt * 128;

    float w0 = gw[0], w1 = gw[1], w2 = gw[2];
    float d0 = df[0], d1 = df[1], d2 = df[2];
    float mx = fmaxf(w0, fmaxf(w1, w2));
    float e0 = expf(w0 - mx), e1 = expf(w1 - mx), e2 = expf(w2 - mx);
    float s0f = 1.f / (1.f + expf(-d0));
    float s1f = 1.f / (1.f + expf(-d1));
    float s2f = 1.f / (1.f + expf(-d2));
    float coef = (e0 * (1.f - s0f) + e1 * (1.f - s1f) + e2 * (1.f - s2f)) / (e0 + e1 + e2);

#pragma unroll
    for (int j = 0; j < 4; j++) {
        const int e = tid + j * 256;
        const int row = e >> 3, c16 = e & 7;
        *(uint4*)((char*)sm + swoff128(row, c16)) =
            *(const uint4*)(q + (row0 + row) * 1024 + n * 64 + c16 * 8);
    }
    for (int e = tid; e < 1152; e += 256) {
        const int t = e >= 576, ee = t ? e - 576 : e;
        const int row = ee >> 3, c16 = ee & 7;
        const __half* src = (t ? kvl : kvh) + (long)bn * 4608 + row * 64 + c16 * 8;
        *(uint4*)((char*)sm + 16384 + t * 10240 + swoff128(row, c16)) =
            *(const uint4*)src;
    }
    __syncthreads();

    float acc[9][4];
#pragma unroll
    for (int i = 0; i < 9; i++)
#pragma unroll
        for (int u = 0; u < 4; u++) acc[i][u] = 0.f;

#pragma unroll
    for (int ks = 0; ks < 4; ks++) {
        uint32_t aF[4];
        ldsm4(aF, sA + swoff128(wid * 16 + (lane & 15), ks * 2 + (lane >> 4)));
        const int brow = ((lane >> 4) << 3) + (lane & 7);
        const int bc16 = ks * 2 + ((lane >> 3) & 1);
#pragma unroll
        for (int nf = 0; nf < 4; nf++) {
            uint32_t bH[4], bL[4];
            ldsm4(bH, sBh + swoff128(nf * 16 + brow, bc16));
            ldsm4(bL, sBl + swoff128(nf * 16 + brow, bc16));
            mma16816h(acc[nf * 2 + 0], aF, bH + 0);
            mma16816h(acc[nf * 2 + 1], aF, bH + 2);
            mma16816h(acc[nf * 2 + 0], aF, bL + 0);
            mma16816h(acc[nf * 2 + 1], aF, bL + 2);
        }
        uint32_t bH[4], bL[4];
        ldsm4(bH, sBh + swoff128(64 + brow, bc16));
        ldsm4(bL, sBl + swoff128(64 + brow, bc16));
        mma16816h(acc[8], aF, bH + 0);
        mma16816h(acc[8], aF, bL + 0);
    }

#pragma unroll
    for (int u = 0; u < 4; u += 2) {
        const int rloc = wid * 16 + (lane >> 2) + (u ? 8 : 0);
        const long gr = row0 + rloc;
        float den = __shfl_sync(0xffffffffu, acc[8][u], lane & ~3) + EPSF;
        const float g = gate[gr];
        const float fac = g / den + (1.f - g) * coef;
#pragma unroll
        for (int ni = 0; ni < 8; ni++) {
            const int c = 2 * (lane & 3) + ni * 8;
            *(__half2*)(cf + gr * 1024 + n * 64 + c) =
                pack_h2(acc[ni][u] * fac, acc[ni][u + 1] * fac);
        }
    }
}

// ================= rope table ==============================================
__global__ void rope_table_kernel(float2* __restrict__ tab)
{
    const int idx = blockIdx.x * 256 + threadIdx.x;
    const int i = idx & 31, s = idx >> 5;
    double p = pow(10000.0, (double)(2 * i) / 64.0);
    float f = (float)s * (1.0f / (float)p);
    tab[idx] = make_float2(cosf(f), sinf(f));
}

// ============ cvt x -> single fp16 + gate (one block per row) ==============
__global__ void cvt_x_gate(const float4* __restrict__ x,
                           const float4* __restrict__ Wg,
                           const float* __restrict__ bg,
                           uint2* __restrict__ xf,
                           float* __restrict__ gout)
{
    const int row = blockIdx.x;
    const int tid = threadIdx.x;
    const long i = (long)row * 256 + tid;
    float4 v = x[i];
    float4 w = Wg[tid];
    float dot = v.x * w.x + v.y * w.y + v.z * w.z + v.w * w.w;

    float f[4] = {v.x, v.y, v.z, v.w};
    unsigned short hs[4];
#pragma unroll
    for (int j = 0; j < 4; j++) {
        __half h = __float2half(f[j]);
        hs[j] = *(unsigned short*)&h;
    }
    uint2 H;
    H.x = (uint32_t)hs[0] | ((uint32_t)hs[1] << 16);
    H.y = (uint32_t)hs[2] | ((uint32_t)hs[3] << 16);
    xf[i] = H;

#pragma unroll
    for (int o = 16; o; o >>= 1) dot += __shfl_down_sync(0xffffffffu, dot, o);
    __shared__ float ws[8];
    if ((tid & 31) == 0) ws[tid >> 5] = dot;
    __syncthreads();
    if (tid == 0) {
        float t = 0.f;
#pragma unroll
        for (int j = 0; j < 8; j++) t += ws[j];
        t += bg[0];
        gout[row] = 1.f / (1.f + expf(-t));
    }
}

// W[K][N] fp32 -> transposed single fp16 [N][K]; z selects which W
__global__ void cvt_w4(const float* __restrict__ W0, const float* __restrict__ W1,
                       const float* __restrict__ W2, const float* __restrict__ W3,
                       __half* __restrict__ h0, __half* __restrict__ h1,
                       __half* __restrict__ h2, __half* __restrict__ h3)
{
    const int z = blockIdx.z;
    const float* W = (z == 0) ? W0 : (z == 1) ? W1 : (z == 2) ? W2 : W3;
    __half* bh = (z == 0) ? h0 : (z == 1) ? h1 : (z == 2) ? h2 : h3;

    __shared__ float t[32][33];
    const int nx = blockIdx.x * 32, kx = blockIdx.y * 32;
    const int tx = threadIdx.x, ty = threadIdx.y;
#pragma unroll
    for (int r = 0; r < 32; r += 8)
        t[ty + r][tx] = W[(long)(kx + ty + r) * 1024 + nx + tx];
    __syncthreads();
#pragma unroll
    for (int r = 0; r < 32; r += 8) {
        float v = t[tx][ty + r];
        long o = (long)(nx + ty + r) * 1024 + kx + tx;
        bh[o] = __float2half(v);
    }
}

// ================= host: tensormap construction ============================
typedef CUresult (*PFN_encodeTiled)(
    CUtensorMap*, CUtensorMapDataType, cuuint32_t, void*,
    const cuuint64_t*, const cuuint64_t*, const cuuint32_t*, const cuuint32_t*,
    CUtensorMapInterleave, CUtensorMapSwizzle, CUtensorMapL2promotion,
    CUtensorMapFloatOOBfill);

static PFN_encodeTiled get_encoder() {
    static PFN_encodeTiled fn = nullptr;
    if (!fn) {
        void* p = nullptr;
        cudaDriverEntryPointQueryResult st;
        cudaGetDriverEntryPointByVersion("cuTensorMapEncodeTiled", &p, 12000,
                                         cudaEnableDefault, &st);
        fn = (PFN_encodeTiled)p;
    }
    return fn;
}

static void make_map(CUtensorMap* m, void* base, uint64_t rows, uint32_t boxy) {
    cuuint64_t dims[2]    = {1024, rows};
    cuuint64_t strides[1] = {2048};
    cuuint32_t box[2]     = {32, boxy};
    cuuint32_t es[2]      = {1, 1};
    get_encoder()(m, CU_TENSOR_MAP_DATA_TYPE_FLOAT16, 2, base, dims, strides,
                  box, es, CU_TENSOR_MAP_INTERLEAVE_NONE,
                  CU_TENSOR_MAP_SWIZZLE_64B, CU_TENSOR_MAP_L2_PROMOTION_L2_128B,
                  CU_TENSOR_MAP_FLOAT_OOB_FILL_NONE);
}

// ---------------------------------------------------------------------------
extern "C" void kernel_launch(void* const* d_in, const int* in_sizes, int n_in,
                              void* d_out, int out_size)
{
    const float* x    = (const float*)d_in[0];
    const float* mask = (const float*)d_in[1];
    const float* Wq   = (const float*)d_in[2];
    const float* bq   = (const float*)d_in[3];
    const float* Wk   = (const float*)d_in[4];
    const float* bk   = (const float*)d_in[5];
    const float* Wv   = (const float*)d_in[6];
    const float* bv   = (const float*)d_in[7];
    const float* Wo   = (const float*)d_in[8];
    const float* bo   = (const float*)d_in[9];
    const float* Wg   = (const float*)d_in[10];
    const float* bg   = (const float*)d_in[11];
    const float* df   = (const float*)d_in[12];
    const float* gw   = (const float*)d_in[13];
    float* out = (float*)d_out;

    float *kvp, *gate;
    float2* tab;
    __half *q16, *kt, *vt, *kvh, *kvl, *af, *bq16, *bk16, *bv16, *bo16;
    cudaGetSymbolAddress((void**)&q16,  g_q16);
    cudaGetSymbolAddress((void**)&kt,   g_kt);
    cudaGetSymbolAddress((void**)&vt,   g_vt);
    cudaGetSymbolAddress((void**)&kvp,  g_kv_part);
    cudaGetSymbolAddress((void**)&kvh,  g_kvt_h);
    cudaGetSymbolAddress((void**)&kvl,  g_kvt_l);
    cudaGetSymbolAddress((void**)&gate, g_gate);
    cudaGetSymbolAddress((void**)&tab,  g_rope);
    cudaGetSymbolAddress((void**)&af,   g_af);
    cudaGetSymbolAddress((void**)&bq16, g_bq16);
    cudaGetSymbolAddress((void**)&bk16, g_bk16);
    cudaGetSymbolAddress((void**)&bv16, g_bv16);
    cudaGetSymbolAddress((void**)&bo16, g_bo16);

    CUtensorMap mAf, mQ, mK, mV, mO;
    make_map(&mAf, af, Msz, 128);
    make_map(&mQ,  bq16, Hsz, 64);
    make_map(&mK,  bk16, Hsz, 64);
    make_map(&mV,  bv16, Hsz, 64);
    make_map(&mO,  bo16, Hsz, 64);

    cudaFuncSetAttribute(gemm_qkv,
                         cudaFuncAttributeMaxDynamicSharedMemorySize, SMEM_GEMM);
    cudaFuncSetAttribute(gemm_out,
                         cudaFuncAttributeMaxDynamicSharedMemorySize, SMEM_GEMM);

    // 1. rope table
    rope_table_kernel<<<Ssz * 32 / 256, 256>>>(tab);
    // 2. activation -> single fp16 + gate
    cvt_x_gate<<<Msz, 256>>>((const float4*)x, (const float4*)Wg, bg,
                             (uint2*)af, gate);
    // 3. weight conversions
    cvt_w4<<<dim3(32, 32, 4), dim3(32, 8)>>>(Wq, Wk, Wv, Wo,
                                             bq16, bk16, bv16, bo16);
    // 4. fused QKV projection; q -> [s][1024], k/v -> transposed fp16
    gemm_qkv<<<dim3(16, 64, 3), 256, SMEM_GEMM>>>(
        mAf, mQ, mK, mV, bq, bk, bv, q16, kt, vt, mask, tab);
    // 5. kv outer-product GEMM (split-K partials)
    gemm_kv<<<dim3(4, 64), 256>>>(vt, kt, kvp);
    // 6. reduce partials + ksum -> kvt hi/lo
    kvt_finalize<<<64, 256>>>(kvp, kt, kvh, kvl);
    // 7. combine GEMM (num + den in one MMA) + gate epilogue -> af fp16
    gemm_cmb<<<dim3(16, 64), 256>>>(q16, kvh, kvl, gate, df, gw, af);
    // 8. output projection
    gemm_out<<<dim3(16, 64), 256, SMEM_GEMM>>>(mAf, mO, bo, out);
}

// round 16
// speedup vs baseline: 1.0733x; 1.0733x over previous
#include <cuda_runtime.h>
#include <cuda.h>
#include <cuda_bf16.h>
#include <cuda_fp16.h>
#include <math.h>
#include <stdint.h>

// Problem constants
#define Bsz 4
#define Ssz 2048
#define Hsz 1024
#define Nh  16
#define Dh  64
#define Msz (Bsz*Ssz)      // 8192
#define EPSF 1e-6f

// ---------------- scratch (static device globals; no allocs allowed) -------
__device__ __half g_q16[Msz*Hsz];         // q (phi'd, scaled) fp16 [s][1024]
__device__ __half g_kt[64*64*Ssz];        // k transposed [bn][kd][s] fp16
__device__ __half g_vt[64*64*Ssz];        // v transposed [bn][vd][s] fp16
__device__ float g_kv_part[4*64*64*64];   // [kc][bn][vd][kd]
__device__ __half g_kvt_h[64*72*64];      // [bn][72][64]: rows0-63 kv, 64 ksum
__device__ __half g_kvt_l[64*72*64];
__device__ float g_gate[Msz];
__device__ float2 g_rope[Ssz*32];         // (cos, sin) per (s, i)
__device__ __half g_af[Msz*Hsz];          // x fp16 (QKV phase), comb fp16 after
__device__ __half g_bq16[Hsz*Hsz];        // Wq single fp16 [N][K]
__device__ __half g_bk16[Hsz*Hsz];
__device__ __half g_bv16[Hsz*Hsz];
__device__ __half g_bo16[Hsz*Hsz];

// ================= low-level helpers =======================================
static __device__ __forceinline__ uint32_t s2u(const void* p) {
    uint32_t a;
    asm("{ .reg .u64 t; cvta.to.shared.u64 t, %1; cvt.u32.u64 %0, t; }"
        : "=r"(a) : "l"(p));
    return a;
}

static __device__ __forceinline__ void ldsm4(uint32_t* r, uint32_t addr) {
    asm volatile("ldmatrix.sync.aligned.m8n8.x4.shared.b16 {%0,%1,%2,%3}, [%4];"
                 : "=r"(r[0]), "=r"(r[1]), "=r"(r[2]), "=r"(r[3]) : "r"(addr));
}

static __device__ __forceinline__ void mma16816h(float* d, const uint32_t* a,
                                                 const uint32_t* b) {
    asm volatile(
        "mma.sync.aligned.m16n8k16.row.col.f32.f16.f16.f32 "
        "{%0,%1,%2,%3}, {%4,%5,%6,%7}, {%8,%9}, {%0,%1,%2,%3};"
        : "+f"(d[0]), "+f"(d[1]), "+f"(d[2]), "+f"(d[3])
        : "r"(a[0]), "r"(a[1]), "r"(a[2]), "r"(a[3]), "r"(b[0]), "r"(b[1]));
}

// 64B-row tile swizzle (TMA SW64 tiles: rows of 32 halves)
static __device__ __forceinline__ uint32_t swoff(int row, int c16) {
    return (uint32_t)(row * 64 + ((c16 ^ ((row >> 1) & 3)) << 4));
}
// 128B-row tile swizzle (plain-load tiles: rows of 64 halves, 8 c16 chunks)
static __device__ __forceinline__ uint32_t swoff128(int row, int c16) {
    return (uint32_t)(row * 128 + ((c16 ^ (row & 7)) << 4));
}

#define MBAR_INIT(m, c) \
    asm volatile("mbarrier.init.shared.b64 [%0], %1;" \
                 :: "r"((uint32_t)(m)), "r"((uint32_t)(c)) : "memory")
#define MBAR_EXPECT(m, b) \
    asm volatile("mbarrier.arrive.expect_tx.shared.b64 _, [%0], %1;" \
                 :: "r"((uint32_t)(m)), "r"((uint32_t)(b)) : "memory")
#define MBAR_ARRIVE_REL(m) \
    asm volatile("mbarrier.arrive.release.cta.shared.b64 _, [%0];" \
                 :: "r"((uint32_t)(m)) : "memory")
#define FENCE_ASYNC() \
    asm volatile("fence.proxy.async.shared::cta;" ::: "memory")

static __device__ __forceinline__ void mbar_wait(uint32_t mbar, uint32_t parity) {
    asm volatile(
        "{\n\t.reg .pred P;\n\t"
        "WL_%=:\n\t"
        "mbarrier.try_wait.parity.acquire.cta.shared::cta.b64 P, [%0], %1, 0x989680;\n\t"
        "@P bra.uni WD_%=;\n\t"
        "bra.uni WL_%=;\n\t"
        "WD_%=:\n\t}"
        :: "r"(mbar), "r"(parity) : "memory");
}

#define TMA2D(sa, mp, cx, cy, mb) \
    asm volatile("cp.async.bulk.tensor.2d.shared::cta.global.tile.mbarrier::complete_tx::bytes " \
                 "[%0], [%1, {%2, %3}], [%4];" \
                 :: "r"((uint32_t)(sa)), "l"(mp), "r"((int)(cx)), "r"((int)(cy)), \
                    "r"((uint32_t)(mb)) : "memory")

__device__ __forceinline__ float phi_fn(float x) {
    float t = (x > 0.f) ? x : expm1f(x);
    return (t + 1.0f) + EPSF;
}

static __device__ __forceinline__ __half2 pack_h2(float a, float b) {
    return __halves2half2(__float2half(a), __float2half(b));
}

// ===== GEMM config: CTA 128x128, BK=64 stages (two 8KB halves/operand) =====
// stage 32KB: [A0 8K][A1 8K][B0 8K][B1 8K]; 3 stages.
// Sync: full[s] (TMA tx) + empty[s] (256 release-arrivals after proxy fence);
// tid0 acquires empty[s] before refilling -> warps free-run across the ring.
#define PSTAGES 3
#define PSTAGE_B 32768
#define NPAIR 16
#define SMEM_GEMM (PSTAGES * PSTAGE_B + 128)

// Interleaved ldsm/MMA slice body, warp-staggered k-slice order (R14, validated).
#define PAIR_BODY(bA, bB)                                                     \
    {                                                                         \
        uint32_t aF[2][2][4], br[2][2][4];                                    \
        {                                                                     \
            const int ks0 = wm & 3;                                           \
            const uint32_t hA = (bA) + (ks0 >> 1) * 8192;                     \
            const int kk = (ks0 & 1) * 2 + a_c16h;                            \
            ldsm4(aF[0][0], hA + swoff(a_row,      kk));                      \
            ldsm4(aF[0][1], hA + swoff(a_row + 16, kk));                      \
        }                                                                     \
        _Pragma("unroll")                                                     \
        for (int ksi = 0; ksi < 4; ksi++) {                                   \
            const int cur = ksi & 1, nxt = cur ^ 1;                           \
            const int ks = (ksi + wm) & 3;                                    \
            const uint32_t hB = (bB) + (ks >> 1) * 8192;                      \
            const int bc = (ks & 1) * 2 + b_c16h;                             \
            ldsm4(br[0][0], hB + swoff(b_row,      bc));                      \
            ldsm4(br[0][1], hB + swoff(b_row + 16, bc));                      \
            if (ksi < 3) {                                                    \
                const int ks2 = (ksi + 1 + wm) & 3;                           \
                const uint32_t hA2 = (bA) + (ks2 >> 1) * 8192;                \
                const int kk2 = (ks2 & 1) * 2 + a_c16h;                       \
                ldsm4(aF[nxt][0], hA2 + swoff(a_row,      kk2));              \
                ldsm4(aF[nxt][1], hA2 + swoff(a_row + 16, kk2));              \
            }                                                                 \
            mma16816h(acc[0][0], aF[cur][0], br[0][0] + 0);                   \
            mma16816h(acc[0][1], aF[cur][0], br[0][0] + 2);                   \
            mma16816h(acc[1][0], aF[cur][1], br[0][0] + 0);                   \
            mma16816h(acc[1][1], aF[cur][1], br[0][0] + 2);                   \
            ldsm4(br[1][0], hB + swoff(b_row + 32, bc));                      \
            mma16816h(acc[0][2], aF[cur][0], br[0][1] + 0);                   \
            mma16816h(acc[0][3], aF[cur][0], br[0][1] + 2);                   \
            mma16816h(acc[1][2], aF[cur][1], br[0][1] + 0);                   \
            mma16816h(acc[1][3], aF[cur][1], br[0][1] + 2);                   \
            ldsm4(br[1][1], hB + swoff(b_row + 48, bc));                      \
            mma16816h(acc[0][4], aF[cur][0], br[1][0] + 0);                   \
            mma16816h(acc[0][5], aF[cur][0], br[1][0] + 2);                   \
            mma16816h(acc[1][4], aF[cur][1], br[1][0] + 0);                   \
            mma16816h(acc[1][5], aF[cur][1], br[1][0] + 2);                   \
            mma16816h(acc[0][6], aF[cur][0], br[1][1] + 0);                   \
            mma16816h(acc[0][7], aF[cur][0], br[1][1] + 2);                   \
            mma16816h(acc[1][6], aF[cur][1], br[1][1] + 0);                   \
            mma16816h(acc[1][7], aF[cur][1], br[1][1] + 2);                   \
        }                                                                     \
    }

// mainloop with decoupled consumer-release pipeline (shared by both GEMMs)
#define GEMM_MAINLOOP(TMA4)                                                   \
    int sp = 0, ph = 0;                                                       \
    for (int p = 0; p < NPAIR; p++) {                                         \
        mbar_wait(mbf + sp * 8, ph);                                          \
        const uint32_t bA = sbase + sp * PSTAGE_B;                            \
        const uint32_t bB = bA + 16384;                                       \
        PAIR_BODY(bA, bB)                                                     \
        FENCE_ASYNC();                                                        \
        MBAR_ARRIVE_REL(mbe + sp * 8);                                        \
        const int np_ = p + PSTAGES;                                          \
        if (np_ < NPAIR && tid == 0) {                                        \
            mbar_wait(mbe + sp * 8, (p / 3) & 1);                             \
            const uint32_t db = sbase + sp * PSTAGE_B;                        \
            MBAR_EXPECT(mbf + sp * 8, PSTAGE_B);                              \
            TMA4(db, np_);                                                    \
        }                                                                     \
        if (++sp == PSTAGES) { sp = 0; ph ^= 1; }                             \
    }

// ========== QKV GEMM: single-product fp16 =================================
// z=0: q -> rope/phi*0.125, fp16 [s][1024]
// z=1: k -> rope/phi*mask, fp16 TRANSPOSED [bn][kd][s]
// z=2: v -> mask, fp16 TRANSPOSED [bn][vd][s]
__global__ __launch_bounds__(256, 2)
void gemm_qkv(const __grid_constant__ CUtensorMap mAf,
              const __grid_constant__ CUtensorMap mB0,
              const __grid_constant__ CUtensorMap mB1,
              const __grid_constant__ CUtensorMap mB2,
              const float* __restrict__ b0, const float* __restrict__ b1,
              const float* __restrict__ b2,
              __half* __restrict__ Cq, __half* __restrict__ KT,
              __half* __restrict__ VT,
              const float* __restrict__ maskp,
              const float2* __restrict__ tab)
{
    extern __shared__ __align__(1024) char smem[];
    const uint32_t sbase = s2u(smem);
    const uint32_t mbf  = sbase + PSTAGES * PSTAGE_B;        // full[3]
    const uint32_t mbe  = mbf + 32;                          // empty[3]
    const int tid = threadIdx.x;
    const int lane = tid & 31, wid = tid >> 5;
    const int wm = wid & 3, wn = wid >> 2;
    const int n0 = blockIdx.x * 128, m0 = blockIdx.y * 128;
    const int z = blockIdx.z;

    const CUtensorMap* pB = (z == 0) ? &mB0 : (z == 1) ? &mB1 : &mB2;
    const float* bias = (z == 0) ? b0 : (z == 1) ? b1 : b2;

    const int a_row  = wm * 32 + (lane & 15);
    const int a_c16h = lane >> 4;
    const int b_row  = wn * 64 + ((lane >> 4) << 3) + (lane & 7);
    const int b_c16h = (lane >> 3) & 1;

    float acc[2][8][4];
#pragma unroll
    for (int mi = 0; mi < 2; mi++)
#pragma unroll
        for (int ni = 0; ni < 8; ni++)
#pragma unroll
            for (int u = 0; u < 4; u++) acc[mi][ni][u] = 0.f;

    if (tid == 0) {
#pragma unroll
        for (int s = 0; s < PSTAGES; s++) {
            MBAR_INIT(mbf + s * 8, 1);
            MBAR_INIT(mbe + s * 8, 256);
        }
    }
    __syncthreads();

#define QTMA4(db, pp) do { \
        TMA2D((db),         &mAf, (pp) * 64,      m0, mbf + sp * 8); \
        TMA2D((db) + 8192,  &mAf, (pp) * 64 + 32, m0, mbf + sp * 8); \
        TMA2D((db) + 16384, pB,   (pp) * 64,      n0, mbf + sp * 8); \
        TMA2D((db) + 24576, pB,   (pp) * 64 + 32, n0, mbf + sp * 8); \
    } while (0)

    if (tid == 0) {
        for (int sp = 0; sp < PSTAGES; sp++) {
            const uint32_t db = sbase + sp * PSTAGE_B;
            MBAR_EXPECT(mbf + sp * 8, PSTAGE_B);
            QTMA4(db, sp);
        }
    }

    GEMM_MAINLOOP(QTMA4)
#undef QTMA4

    // ---------------- epilogue ----------------
    const int r0 = m0 + wm * 32 + (lane >> 2);
    const int nb0 = n0 + wn * 64 + 2 * (lane & 3);

    if (z == 0) {
#pragma unroll
        for (int mi = 0; mi < 2; mi++) {
#pragma unroll
            for (int uu = 0; uu < 4; uu += 2) {
                const int r = r0 + mi * 16 + (uu ? 8 : 0);
                const int srow = r & (Ssz - 1);
#pragma unroll
                for (int ni = 0; ni < 4; ni++) {
                    float o1[2], o2[2];
#pragma unroll
                    for (int e = 0; e < 2; e++) {
                        const int i = 2 * (lane & 3) + ni * 8 + e;
                        const int c = nb0 + ni * 8 + e;
                        float x1 = acc[mi][ni][uu + e]     + bias[c];
                        float x2 = acc[mi][ni + 4][uu + e] + bias[c + 32];
                        float2 cs = tab[srow * 32 + i];
                        float r1 = x1 * cs.x - x2 * cs.y;
                        float r2 = x2 * cs.x + x1 * cs.y;
                        o1[e] = phi_fn(r1) * 0.125f;
                        o2[e] = phi_fn(r2) * 0.125f;
                    }
                    const int c = nb0 + ni * 8;
                    *(__half2*)(Cq + (long)r * 1024 + c)      = pack_h2(o1[0], o1[1]);
                    *(__half2*)(Cq + (long)r * 1024 + c + 32) = pack_h2(o2[0], o2[1]);
                }
            }
        }
        return;
    }

    // k/v: transposed store via smem staging. ts[c_local][rloc], pitch 136.
    __syncthreads();                 // ring fully consumed by all warps
    __half* ts = (__half*)smem;
    const int rb = wm * 32 + (lane >> 2);
    const int cb = wn * 64 + 2 * (lane & 3);

#pragma unroll
    for (int mi = 0; mi < 2; mi++) {
#pragma unroll
        for (int uu = 0; uu < 4; uu += 2) {
            const int rloc = rb + mi * 16 + (uu ? 8 : 0);
            const int r = m0 + rloc;
            const int srow = r & (Ssz - 1);
            const float msk = maskp[r];
            if (z == 2) {
#pragma unroll
                for (int ni = 0; ni < 8; ni++) {
#pragma unroll
                    for (int e = 0; e < 2; e++) {
                        const int cl = cb + ni * 8 + e;
                        float val = (acc[mi][ni][uu + e] + bias[n0 + cl]) * msk;
                        ts[cl * 136 + rloc] = __float2half(val);
                    }
                }
            } else {
#pragma unroll
                for (int ni = 0; ni < 4; ni++) {
#pragma unroll
                    for (int e = 0; e < 2; e++) {
                        const int i = 2 * (lane & 3) + ni * 8 + e;
                        const int cl = cb + ni * 8 + e;
                        float x1 = acc[mi][ni][uu + e]     + bias[n0 + cl];
                        float x2 = acc[mi][ni + 4][uu + e] + bias[n0 + cl + 32];
                        float2 cs = tab[srow * 32 + i];
                        float r1 = x1 * cs.x - x2 * cs.y;
                        float r2 = x2 * cs.x + x1 * cs.y;
                        ts[cl * 136 + rloc]        = __float2half(phi_fn(r1) * msk);
                        ts[(cl + 32) * 136 + rloc] = __float2half(phi_fn(r2) * msk);
                    }
                }
            }
        }
    }
    __syncthreads();

    __half* T = (z == 1) ? KT : VT;
    const int b = m0 >> 11;
    const int sb = m0 & (Ssz - 1);
#pragma unroll
    for (int i = 0; i < 8; i++) {
        const int e = tid + i * 256;
        const int c = e >> 4, ch = e & 15, rl = ch * 8;
        uint4 val = *(uint4*)&ts[c * 136 + rl];
        const int bn = b * 16 + (n0 >> 6) + (c >> 6);
        const int d = c & 63;
        *(uint4*)(T + ((long)(bn * 64 + d)) * Ssz + sb + rl) = val;
    }
}

// ===== OUT GEMM: single-product fp16, same pipeline, fp32 store ============
__global__ __launch_bounds__(256, 2)
void gemm_out(const __grid_constant__ CUtensorMap mAf,
              const __grid_constant__ CUtensorMap mB,
              const float* __restrict__ bias, float* __restrict__ C)
{
    extern __shared__ __align__(1024) char smem[];
    const uint32_t sbase = s2u(smem);
    const uint32_t mbf  = sbase + PSTAGES * PSTAGE_B;
    const uint32_t mbe  = mbf + 32;
    const int tid = threadIdx.x;
    const int lane = tid & 31, wid = tid >> 5;
    const int wm = wid & 3, wn = wid >> 2;
    const int n0 = blockIdx.x * 128, m0 = blockIdx.y * 128;

    const int a_row  = wm * 32 + (lane & 15);
    const int a_c16h = lane >> 4;
    const int b_row  = wn * 64 + ((lane >> 4) << 3) + (lane & 7);
    const int b_c16h = (lane >> 3) & 1;

    float acc[2][8][4];
#pragma unroll
    for (int mi = 0; mi < 2; mi++)
#pragma unroll
        for (int ni = 0; ni < 8; ni++)
#pragma unroll
            for (int u = 0; u < 4; u++) acc[mi][ni][u] = 0.f;

    if (tid == 0) {
#pragma unroll
        for (int s = 0; s < PSTAGES; s++) {
            MBAR_INIT(mbf + s * 8, 1);
            MBAR_INIT(mbe + s * 8, 256);
        }
    }
    __syncthreads();

#define OTMA4(db, pp) do { \
        TMA2D((db),         &mAf, (pp) * 64,      m0, mbf + sp * 8); \
        TMA2D((db) + 8192,  &mAf, (pp) * 64 + 32, m0, mbf + sp * 8); \
        TMA2D((db) + 16384, &mB,  (pp) * 64,      n0, mbf + sp * 8); \
        TMA2D((db) + 24576, &mB,  (pp) * 64 + 32, n0, mbf + sp * 8); \
    } while (0)

    if (tid == 0) {
        for (int sp = 0; sp < PSTAGES; sp++) {
            const uint32_t db = sbase + sp * PSTAGE_B;
            MBAR_EXPECT(mbf + sp * 8, PSTAGE_B);
            OTMA4(db, sp);
        }
    }

    GEMM_MAINLOOP(OTMA4)
#undef OTMA4

    const int r0 = m0 + wm * 32 + (lane >> 2);
    const int nb0 = n0 + wn * 64 + 2 * (lane & 3);
#pragma unroll
    for (int mi = 0; mi < 2; mi++) {
#pragma unroll
        for (int ni = 0; ni < 8; ni++) {
            const int r = r0 + mi * 16;
            const int c = nb0 + ni * 8;
            float2 bb = *(const float2*)(bias + c);
            *(float2*)(C + (long)r * 1024 + c) =
                make_float2(acc[mi][ni][0] + bb.x, acc[mi][ni][1] + bb.y);
            *(float2*)(C + (long)(r + 8) * 1024 + c) =
                make_float2(acc[mi][ni][2] + bb.x, acc[mi][ni][3] + bb.y);
        }
    }
}

// ============ gemm_kv: D[vd][kd] = sum_s v_t[vd][s] * k_t[kd][s] ===========
__global__ __launch_bounds__(256, 4)
void gemm_kv(const __half* __restrict__ vt, const __half* __restrict__ kt,
             float* __restrict__ part)
{
    __shared__ __align__(16) char sm[16384];
    const uint32_t sA = s2u(sm), sB = sA + 8192;
    const int tid = threadIdx.x;
    const int lane = tid & 31, wid = tid >> 5;
    const int wm = wid & 3, wn = wid >> 2;
    const int kc = blockIdx.x, head = blockIdx.y;

    float acc[4][4];
#pragma unroll
    for (int i = 0; i < 4; i++)
#pragma unroll
        for (int u = 0; u < 4; u++) acc[i][u] = 0.f;

    for (int sc = 0; sc < 8; sc++) {
        const int sg = kc * 512 + sc * 64;
#pragma unroll
        for (int j = 0; j < 4; j++) {
            const int e = tid + j * 256;
            const int t = e >> 9, row = (e >> 3) & 63, c16 = e & 7;
            const __half* src = (t ? kt : vt) +
                ((long)(head * 64 + row)) * Ssz + sg + c16 * 8;
            *(uint4*)((char*)sm + t * 8192 + swoff128(row, c16)) =
                *(const uint4*)src;
        }
        __syncthreads();

#pragma unroll
        for (int ks = 0; ks < 4; ks++) {
            uint32_t aF[4];
            ldsm4(aF, sA + swoff128(wm * 16 + (lane & 15), ks * 2 + (lane >> 4)));
#pragma unroll
            for (int nb = 0; nb < 2; nb++) {
                uint32_t bF[4];
                ldsm4(bF, sB + swoff128(wn * 32 + nb * 16 +
                                        ((lane >> 4) << 3) + (lane & 7),
                                        ks * 2 + ((lane >> 3) & 1)));
                mma16816h(acc[nb * 2 + 0], aF, bF + 0);
                mma16816h(acc[nb * 2 + 1], aF, bF + 2);
            }
        }
        __syncthreads();
    }

    float* pb = part + ((long)(kc * 64 + head)) * 4096;
    const int rb = wm * 16 + (lane >> 2);
    const int cb = wn * 32 + 2 * (lane & 3);
#pragma unroll
    for (int nf = 0; nf < 4; nf++) {
        const int c = cb + nf * 8;
        *(float2*)(pb + rb * 64 + c)       = make_float2(acc[nf][0], acc[nf][1]);
        *(float2*)(pb + (rb + 8) * 64 + c) = make_float2(acc[nf][2], acc[nf][3]);
    }
}

// ==== kvt_finalize: reduce partials -> kvt hi/lo; row64 = ksum; 65-71 = 0 ==
__global__ void kvt_finalize(const float* __restrict__ part,
                             const __half* __restrict__ kt,
                             __half* __restrict__ kvh, __half* __restrict__ kvl)
{
    const int head = blockIdx.x;
    const int tid = threadIdx.x;
    const long ob = (long)head * 72 * 64;

    for (int e = tid; e < 4096; e += 256) {
        float s = 0.f;
#pragma unroll
        for (int c = 0; c < 4; c++)
            s += part[((long)(c * 64 + head)) * 4096 + e];
        __half h = __float2half(s);
        kvh[ob + e] = h;
        kvl[ob + e] = __float2half(s - __half2float(h));
    }

    const int kd = tid >> 2, qtr = tid & 3;
    const __half* kr = kt + ((long)(head * 64 + kd)) * Ssz + qtr * 512;
    float s = 0.f;
#pragma unroll 8
    for (int i = 0; i < 64; i++) {
        uint4 u = *(const uint4*)(kr + i * 8);
        float2 a = __half22float2(*(__half2*)&u.x);
        float2 b = __half22float2(*(__half2*)&u.y);
        float2 c = __half22float2(*(__half2*)&u.z);
        float2 d = __half22float2(*(__half2*)&u.w);
        s += a.x + a.y + b.x + b.y + c.x + c.y + d.x + d.y;
    }
    s += __shfl_down_sync(0xffffffffu, s, 2);
    s += __shfl_down_sync(0xffffffffu, s, 1);
    if (qtr == 0) {
        __half h = __float2half(s);
        kvh[ob + 64 * 64 + kd] = h;
        kvl[ob + 64 * 64 + kd] = __float2half(s - __half2float(h));
    }

    for (int e = tid; e < 7 * 64; e += 256) {
        kvh[ob + 65 * 64 + e] = __float2half(0.f);
        kvl[ob + 65 * 64 + e] = __float2half(0.f);
    }
}

// ==== gemm_cmb: num/den = q @ kvt^T (hi+lo); gate epilogue -> comb fp16 ====
__global__ __launch_bounds__(256, 2)
void gemm_cmb(const __half* __restrict__ q,
              const __half* __restrict__ kvh, const __half* __restrict__ kvl,
              const float* __restrict__ gate,
              const float* __restrict__ df, const float* __restrict__ gw,
              __half* __restrict__ cf)
{
    __shared__ __align__(16) char sm[16384 + 2 * 10240];
    const uint32_t sA = s2u(sm);
    const uint32_t sBh = sA + 16384, sBl = sBh + 10240;
    const int tid = threadIdx.x;
    const int lane = tid & 31, wid = tid >> 5;
    const int mt = blockIdx.x, bn = blockIdx.y;
    const int b = bn >> 4, n = bn & 15;
    const long row0 = (long)b * Ssz + mt * 128;

    float w0 = gw[0], w1 = gw[1], w2 = gw[2];
    float d0 = df[0], d1 = df[1], d2 = df[2];
    float mx = fmaxf(w0, fmaxf(w1, w2));
    float e0 = expf(w0 - mx), e1 = expf(w1 - mx), e2 = expf(w2 - mx);
    float s0f = 1.f / (1.f + expf(-d0));
    float s1f = 1.f / (1.f + expf(-d1));
    float s2f = 1.f / (1.f + expf(-d2));
    float coef = (e0 * (1.f - s0f) + e1 * (1.f - s1f) + e2 * (1.f - s2f)) / (e0 + e1 + e2);

#pragma unroll
    for (int j = 0; j < 4; j++) {
        const int e = tid + j * 256;
        const int row = e >> 3, c16 = e & 7;
        *(uint4*)((char*)sm + swoff128(row, c16)) =
            *(const uint4*)(q + (row0 + row) * 1024 + n * 64 + c16 * 8);
    }
    for (int e = tid; e < 1152; e += 256) {
        const int t = e >= 576, ee = t ? e - 576 : e;
        const int row = ee >> 3, c16 = ee & 7;
        const __half* src = (t ? kvl : kvh) + (long)bn * 4608 + row * 64 + c16 * 8;
        *(uint4*)((char*)sm + 16384 + t * 10240 + swoff128(row, c16)) =
            *(const uint4*)src;
    }
    __syncthreads();

    float acc[9][4];
#pragma unroll
    for (int i = 0; i < 9; i++)
#pragma unroll
        for (int u = 0; u < 4; u++) acc[i][u] = 0.f;

#pragma unroll
    for (int ks = 0; ks < 4; ks++) {
        uint32_t aF[4];
        ldsm4(aF, sA + swoff128(wid * 16 + (lane & 15), ks * 2 + (lane >> 4)));
        const int brow = ((lane >> 4) << 3) + (lane & 7);
        const int bc16 = ks * 2 + ((lane >> 3) & 1);
#pragma unroll
        for (int nf = 0; nf < 4; nf++) {
            uint32_t bH[4], bL[4];
            ldsm4(bH, sBh + swoff128(nf * 16 + brow, bc16));
            ldsm4(bL, sBl + swoff128(nf * 16 + brow, bc16));
            mma16816h(acc[nf * 2 + 0], aF, bH + 0);
            mma16816h(acc[nf * 2 + 1], aF, bH + 2);
            mma16816h(acc[nf * 2 + 0], aF, bL + 0);
            mma16816h(acc[nf * 2 + 1], aF, bL + 2);
        }
        uint32_t bH[4], bL[4];
        ldsm4(bH, sBh + swoff128(64 + brow, bc16));
        ldsm4(bL, sBl + swoff128(64 + brow, bc16));
        mma16816h(acc[8], aF, bH + 0);
        mma16816h(acc[8], aF, bL + 0);
    }

#pragma unroll
    for (int u = 0; u < 4; u += 2) {
        const int rloc = wid * 16 + (lane >> 2) + (u ? 8 : 0);
        const long gr = row0 + rloc;
        float den = __shfl_sync(0xffffffffu, acc[8][u], lane & ~3) + EPSF;
        const float g = gate[gr];
        const float fac = g / den + (1.f - g) * coef;
#pragma unroll
        for (int ni = 0; ni < 8; ni++) {
            const int c = 2 * (lane & 3) + ni * 8;
            *(__half2*)(cf + gr * 1024 + n * 64 + c) =
                pack_h2(acc[ni][u] * fac, acc[ni][u + 1] * fac);
        }
    }
}

// ================= rope table ==============================================
__global__ void rope_table_kernel(float2* __restrict__ tab)
{
    const int idx = blockIdx.x * 256 + threadIdx.x;
    const int i = idx & 31, s = idx >> 5;
    double p = pow(10000.0, (double)(2 * i) / 64.0);
    float f = (float)s * (1.0f / (float)p);
    tab[idx] = make_float2(cosf(f), sinf(f));
}

// ============ cvt x -> single fp16 + gate (one block per row) ==============
__global__ void cvt_x_gate(const float4* __restrict__ x,
                           const float4* __restrict__ Wg,
                           const float* __restrict__ bg,
                           uint2* __restrict__ xf,
                           float* __restrict__ gout)
{
    const int row = blockIdx.x;
    const int tid = threadIdx.x;
    const long i = (long)row * 256 + tid;
    float4 v = x[i];
    float4 w = Wg[tid];
    float dot = v.x * w.x + v.y * w.y + v.z * w.z + v.w * w.w;

    float f[4] = {v.x, v.y, v.z, v.w};
    unsigned short hs[4];
#pragma unroll
    for (int j = 0; j < 4; j++) {
        __half h = __float2half(f[j]);
        hs[j] = *(unsigned short*)&h;
    }
    uint2 H;
    H.x = (uint32_t)hs[0] | ((uint32_t)hs[1] << 16);
    H.y = (uint32_t)hs[2] | ((uint32_t)hs[3] << 16);
    xf[i] = H;

#pragma unroll
    for (int o = 16; o; o >>= 1) dot += __shfl_down_sync(0xffffffffu, dot, o);
    __shared__ float ws[8];
    if ((tid & 31) == 0) ws[tid >> 5] = dot;
    __syncthreads();
    if (tid == 0) {
        float t = 0.f;
#pragma unroll
        for (int j = 0; j < 8; j++) t += ws[j];
        t += bg[0];
        gout[row] = 1.f / (1.f + expf(-t));
    }
}

// W[K][N] fp32 -> transposed single fp16 [N][K]; z selects which W
__global__ void cvt_w4(const float* __restrict__ W0, const float* __restrict__ W1,
                       const float* __restrict__ W2, const float* __restrict__ W3,
                       __half* __restrict__ h0, __half* __restrict__ h1,
                       __half* __restrict__ h2, __half* __restrict__ h3)
{
    const int z = blockIdx.z;
    const float* W = (z == 0) ? W0 : (z == 1) ? W1 : (z == 2) ? W2 : W3;
    __half* bh = (z == 0) ? h0 : (z == 1) ? h1 : (z == 2) ? h2 : h3;

    __shared__ float t[32][33];
    const int nx = blockIdx.x * 32, kx = blockIdx.y * 32;
    const int tx = threadIdx.x, ty = threadIdx.y;
#pragma unroll
    for (int r = 0; r < 32; r += 8)
        t[ty + r][tx] = W[(long)(kx + ty + r) * 1024 + nx + tx];
    __syncthreads();
#pragma unroll
    for (int r = 0; r < 32; r += 8) {
        float v = t[tx][ty + r];
        long o = (long)(nx + ty + r) * 1024 + kx + tx;
        bh[o] = __float2half(v);
    }
}

// ================= host: tensormap construction ============================
typedef CUresult (*PFN_encodeTiled)(
    CUtensorMap*, CUtensorMapDataType, cuuint32_t, void*,
    const cuuint64_t*, const cuuint64_t*, const cuuint32_t*, const cuuint32_t*,
    CUtensorMapInterleave, CUtensorMapSwizzle, CUtensorMapL2promotion,
    CUtensorMapFloatOOBfill);

static PFN_encodeTiled get_encoder() {
    static PFN_encodeTiled fn = nullptr;
    if (!fn) {
        void* p = nullptr;
        cudaDriverEntryPointQueryResult st;
        cudaGetDriverEntryPointByVersion("cuTensorMapEncodeTiled", &p, 12000,
                                         cudaEnableDefault, &st);
        fn = (PFN_encodeTiled)p;
    }
    return fn;
}

static void make_map(CUtensorMap* m, void* base, uint64_t rows) {
    cuuint64_t dims[2]    = {1024, rows};
    cuuint64_t strides[1] = {2048};
    cuuint32_t box[2]     = {32, 128};
    cuuint32_t es[2]      = {1, 1};
    get_encoder()(m, CU_TENSOR_MAP_DATA_TYPE_FLOAT16, 2, base, dims, strides,
                  box, es, CU_TENSOR_MAP_INTERLEAVE_NONE,
                  CU_TENSOR_MAP_SWIZZLE_64B, CU_TENSOR_MAP_L2_PROMOTION_L2_128B,
                  CU_TENSOR_MAP_FLOAT_OOB_FILL_NONE);
}

// ---------------------------------------------------------------------------
extern "C" void kernel_launch(void* const* d_in, const int* in_sizes, int n_in,
                              void* d_out, int out_size)
{
    const float* x    = (const float*)d_in[0];
    const float* mask = (const float*)d_in[1];
    const float* Wq   = (const float*)d_in[2];
    const float* bq   = (const float*)d_in[3];
    const float* Wk   = (const float*)d_in[4];
    const float* bk   = (const float*)d_in[5];
    const float* Wv   = (const float*)d_in[6];
    const float* bv   = (const float*)d_in[7];
    const float* Wo   = (const float*)d_in[8];
    const float* bo   = (const float*)d_in[9];
    const float* Wg   = (const float*)d_in[10];
    const float* bg   = (const float*)d_in[11];
    const float* df   = (const float*)d_in[12];
    const float* gw   = (const float*)d_in[13];
    float* out = (float*)d_out;

    float *kvp, *gate;
    float2* tab;
    __half *q16, *kt, *vt, *kvh, *kvl, *af, *bq16, *bk16, *bv16, *bo16;
    cudaGetSymbolAddress((void**)&q16,  g_q16);
    cudaGetSymbolAddress((void**)&kt,   g_kt);
    cudaGetSymbolAddress((void**)&vt,   g_vt);
    cudaGetSymbolAddress((void**)&kvp,  g_kv_part);
    cudaGetSymbolAddress((void**)&kvh,  g_kvt_h);
    cudaGetSymbolAddress((void**)&kvl,  g_kvt_l);
    cudaGetSymbolAddress((void**)&gate, g_gate);
    cudaGetSymbolAddress((void**)&tab,  g_rope);
    cudaGetSymbolAddress((void**)&af,   g_af);
    cudaGetSymbolAddress((void**)&bq16, g_bq16);
    cudaGetSymbolAddress((void**)&bk16, g_bk16);
    cudaGetSymbolAddress((void**)&bv16, g_bv16);
    cudaGetSymbolAddress((void**)&bo16, g_bo16);

    CUtensorMap mAf, mQ, mK, mV, mO;
    make_map(&mAf, af, Msz);
    make_map(&mQ,  bq16, Hsz);
    make_map(&mK,  bk16, Hsz);
    make_map(&mV,  bv16, Hsz);
    make_map(&mO,  bo16, Hsz);

    cudaFuncSetAttribute(gemm_qkv,
                         cudaFuncAttributeMaxDynamicSharedMemorySize, SMEM_GEMM);
    cudaFuncSetAttribute(gemm_out,
                         cudaFuncAttributeMaxDynamicSharedMemorySize, SMEM_GEMM);

    // 1. rope table
    rope_table_kernel<<<Ssz * 32 / 256, 256>>>(tab);
    // 2. activation -> single fp16 + gate
    cvt_x_gate<<<Msz, 256>>>((const float4*)x, (const float4*)Wg, bg,
                             (uint2*)af, gate);
    // 3. weight conversions
    cvt_w4<<<dim3(32, 32, 4), dim3(32, 8)>>>(Wq, Wk, Wv, Wo,
                                             bq16, bk16, bv16, bo16);
    // 4. fused QKV projection; q -> [s][1024], k/v -> transposed fp16
    gemm_qkv<<<dim3(8, 64, 3), 256, SMEM_GEMM>>>(
        mAf, mQ, mK, mV, bq, bk, bv, q16, kt, vt, mask, tab);
    // 5. kv outer-product GEMM (split-K partials)
    gemm_kv<<<dim3(4, 64), 256>>>(vt, kt, kvp);
    // 6. reduce partials + ksum -> kvt hi/lo
    kvt_finalize<<<64, 256>>>(kvp, kt, kvh, kvl);
    // 7. combine GEMM (num + den in one MMA) + gate epilogue -> af fp16
    gemm_cmb<<<dim3(16, 64), 256>>>(q16, kvh, kvl, gate, df, gw, af);
    // 8. output projection
    gemm_out<<<dim3(8, 64), 256, SMEM_GEMM>>>(mAf, mO, bo, out);
}